// round 3
// baseline (speedup 1.0000x reference)
#include <cuda_runtime.h>
#include <math.h>

#define Nn 1024
#define Dd 1024
#define Pp 64
#define Gg 16
#define DK 64
#define MI 8

// Scratch (allocation-free rule: __device__ globals)
__device__ float g_q[Nn * Dd];                 // q[i, g*64+d]
__device__ float g_kT[Dd * Nn];                // kT[g*64+d, j]
__device__ float g_v2[Nn * Dd];                // v2[j, g*64+o]  (= roi @ blockdiag(W_out))
__device__ float g_aff[(size_t)Nn * Gg * Nn];  // aff[i, g, j]

// ---------------------------------------------------------------------------
// K1: three [1024,1024]x[1024,1024] GEMMs (z=0: Q, z=1: K^T, z=2: V2)
// ---------------------------------------------------------------------------
__global__ void __launch_bounds__(256) k_gemm3(
    const float* __restrict__ roi,
    const float* __restrict__ Wq, const float* __restrict__ bq,
    const float* __restrict__ Wk, const float* __restrict__ bk,
    const float* __restrict__ Wout)
{
    const int z = blockIdx.z;
    const int rowBase = blockIdx.y * 64;
    const int colBase = blockIdx.x * 64;
    __shared__ float As[16][64];
    __shared__ float Bs[16][68];
    const int tx = threadIdx.x & 15;
    const int ty = threadIdx.x >> 4;
    float acc[4][4] = {};

    for (int k0 = 0; k0 < Dd; k0 += 16) {
        #pragma unroll
        for (int l = threadIdx.x; l < 1024; l += 256) {
            int r = l >> 4, kk = l & 15;
            As[kk][r] = roi[(size_t)(rowBase + r) * Dd + k0 + kk];
        }
        #pragma unroll
        for (int l = threadIdx.x; l < 1024; l += 256) {
            int kk = l >> 6, c = l & 63;
            int col = colBase + c;
            int kg = k0 + kk;
            float v;
            if (z == 0)      v = Wq[(size_t)kg * Dd + col];
            else if (z == 1) v = Wk[(size_t)kg * Dd + col];
            else {
                int gg = col >> 6, oo = col & 63;
                v = Wout[((size_t)gg * Dd + kg) * DK + oo];
            }
            Bs[kk][c] = v;
        }
        __syncthreads();
        #pragma unroll
        for (int kk = 0; kk < 16; kk++) {
            float a[4], b[4];
            #pragma unroll
            for (int r = 0; r < 4; r++) a[r] = As[kk][ty * 4 + r];
            #pragma unroll
            for (int c = 0; c < 4; c++) b[c] = Bs[kk][tx * 4 + c];
            #pragma unroll
            for (int r = 0; r < 4; r++)
                #pragma unroll
                for (int c = 0; c < 4; c++)
                    acc[r][c] += a[r] * b[c];
        }
        __syncthreads();
    }

    #pragma unroll
    for (int r = 0; r < 4; r++) {
        int row = rowBase + ty * 4 + r;
        #pragma unroll
        for (int c = 0; c < 4; c++) {
            int col = colBase + tx * 4 + c;
            float v = acc[r][c];
            if (z == 0)      g_q[(size_t)row * Dd + col] = v + bq[col];
            else if (z == 1) g_kT[(size_t)col * Nn + row] = v + bk[col];
            else             g_v2[(size_t)row * Dd + col] = v;
        }
    }
}

// ---------------------------------------------------------------------------
// K2: PE branch. aff[i,g,j] = (tanh(pe[i,j,:] @ W1 + b1) @ W2 + b2)[g]
// One thread per (i,j) row; 128 rows per block; W1/W2 + pe tile in smem.
// ---------------------------------------------------------------------------
__global__ void __launch_bounds__(128) k_pe(
    const float* __restrict__ pe,
    const float* __restrict__ W1, const float* __restrict__ b1,
    const float* __restrict__ W2, const float* __restrict__ b2)
{
    extern __shared__ float sm[];
    float* w1  = sm;           // 4096
    float* w2  = w1 + 4096;    // 1024
    float* bb1 = w2 + 1024;    // 64
    float* bb2 = bb1 + 64;     // 16
    float* pes = bb2 + 16;     // 128 * 65
    const int tid = threadIdx.x;

    for (int l = tid; l < 4096; l += 128) w1[l] = W1[l];
    for (int l = tid; l < 1024; l += 128) w2[l] = W2[l];
    if (tid < 64) bb1[tid] = b1[tid];
    if (tid < 16) bb2[tid] = b2[tid];

    const size_t base = (size_t)blockIdx.x * 128 * 64;
    for (int l = tid; l < 128 * 64; l += 128) {
        int r = l >> 6, p = l & 63;
        pes[r * 65 + p] = pe[base + l];
    }
    __syncthreads();

    float pr[64];
    #pragma unroll
    for (int p = 0; p < 64; p++) pr[p] = pes[tid * 65 + p];

    float acc[16];
    #pragma unroll
    for (int g = 0; g < 16; g++) acc[g] = bb2[g];

    #pragma unroll 1
    for (int c0 = 0; c0 < 64; c0 += 4) {
        float4 h = make_float4(bb1[c0], bb1[c0 + 1], bb1[c0 + 2], bb1[c0 + 3]);
        #pragma unroll
        for (int p = 0; p < 64; p++) {
            float4 w = *(const float4*)&w1[p * 64 + c0];
            h.x += pr[p] * w.x; h.y += pr[p] * w.y;
            h.z += pr[p] * w.z; h.w += pr[p] * w.w;
        }
        h.x = tanhf(h.x); h.y = tanhf(h.y);
        h.z = tanhf(h.z); h.w = tanhf(h.w);
        #pragma unroll
        for (int cc = 0; cc < 4; cc++) {
            float hv = (&h.x)[cc];
            #pragma unroll
            for (int gq = 0; gq < 4; gq++) {
                float4 w = *(const float4*)&w2[(c0 + cc) * 16 + gq * 4];
                acc[gq * 4 + 0] += hv * w.x;
                acc[gq * 4 + 1] += hv * w.y;
                acc[gq * 4 + 2] += hv * w.z;
                acc[gq * 4 + 3] += hv * w.w;
            }
        }
    }

    const size_t row = (size_t)blockIdx.x * 128 + tid;
    const int i = (int)(row >> 10), j = (int)(row & 1023);
    #pragma unroll
    for (int g = 0; g < 16; g++)
        g_aff[((size_t)i * 16 + g) * 1024 + j] = acc[g];
}

// ---------------------------------------------------------------------------
// K3: fused scores + softmax + P@V2. One block handles MI=8 query rows of
// one group g (L2 reuse of kT/v2 g-slices across blocks with same g).
// ---------------------------------------------------------------------------
__global__ void __launch_bounds__(256) k_attn(
    const float* __restrict__ bout, float* __restrict__ out)
{
    const int g = blockIdx.y;
    const int i0 = blockIdx.x * MI;
    __shared__ float q_s[64][MI];
    __shared__ float p_s[1024][MI];
    __shared__ float red[MI][8];
    __shared__ float mval[MI], isum[MI];
    __shared__ float oacc[4][MI][64];
    const int tid = threadIdx.x;

    for (int l = tid; l < 64 * MI; l += 256) {
        int d = l >> 3, ii = l & 7;
        q_s[d][ii] = g_q[(size_t)(i0 + ii) * Dd + g * 64 + d];
    }
    __syncthreads();

    float s[MI][4];
    #pragma unroll
    for (int ii = 0; ii < MI; ii++)
        #pragma unroll
        for (int t = 0; t < 4; t++) s[ii][t] = 0.f;

    // scores: s[ii][t] = q[i0+ii,g,:] . k[j,g,:]  for j = tid + 256*t
    for (int d = 0; d < 64; d++) {
        const float* kr = g_kT + (size_t)(g * 64 + d) * Nn;
        float kv[4];
        #pragma unroll
        for (int t = 0; t < 4; t++) kv[t] = kr[tid + 256 * t];
        float4 qa = *(const float4*)&q_s[d][0];
        float4 qb = *(const float4*)&q_s[d][4];
        #pragma unroll
        for (int t = 0; t < 4; t++) {
            s[0][t] += qa.x * kv[t]; s[1][t] += qa.y * kv[t];
            s[2][t] += qa.z * kv[t]; s[3][t] += qa.w * kv[t];
            s[4][t] += qb.x * kv[t]; s[5][t] += qb.y * kv[t];
            s[6][t] += qb.z * kv[t]; s[7][t] += qb.w * kv[t];
        }
    }

    // weighted_aff = aff_weight * (score / sqrt(64))
    #pragma unroll
    for (int ii = 0; ii < MI; ii++) {
        const float* ar = g_aff + ((size_t)(i0 + ii) * 16 + g) * 1024;
        #pragma unroll
        for (int t = 0; t < 4; t++)
            s[ii][t] = ar[tid + 256 * t] * (s[ii][t] * 0.125f);
    }

    // row max
    #pragma unroll
    for (int ii = 0; ii < MI; ii++) {
        float m = fmaxf(fmaxf(s[ii][0], s[ii][1]), fmaxf(s[ii][2], s[ii][3]));
        #pragma unroll
        for (int o = 16; o; o >>= 1) m = fmaxf(m, __shfl_xor_sync(0xffffffffu, m, o));
        if ((tid & 31) == 0) red[ii][tid >> 5] = m;
    }
    __syncthreads();
    if (tid < 64) {
        int ii = tid >> 3, w = tid & 7;
        float v = red[ii][w];
        #pragma unroll
        for (int o = 4; o; o >>= 1) v = fmaxf(v, __shfl_xor_sync(0xffffffffu, v, o));
        if (w == 0) mval[ii] = v;
    }
    __syncthreads();

    // exp + row sum
    #pragma unroll
    for (int ii = 0; ii < MI; ii++) {
        float M = mval[ii];
        float su = 0.f;
        #pragma unroll
        for (int t = 0; t < 4; t++) {
            float ev = __expf(s[ii][t] - M);
            s[ii][t] = ev;
            su += ev;
        }
        #pragma unroll
        for (int o = 16; o; o >>= 1) su += __shfl_xor_sync(0xffffffffu, su, o);
        if ((tid & 31) == 0) red[ii][tid >> 5] = su;
    }
    __syncthreads();
    if (tid < 64) {
        int ii = tid >> 3, w = tid & 7;
        float v = red[ii][w];
        #pragma unroll
        for (int o = 4; o; o >>= 1) v += __shfl_xor_sync(0xffffffffu, v, o);
        if (w == 0) isum[ii] = 1.0f / v;
    }

    // stage unnormalized p into smem as [j][ii]
    #pragma unroll
    for (int t = 0; t < 4; t++) {
        int j = tid + 256 * t;
        *(float4*)&p_s[j][0] = make_float4(s[0][t], s[1][t], s[2][t], s[3][t]);
        *(float4*)&p_s[j][4] = make_float4(s[4][t], s[5][t], s[6][t], s[7][t]);
    }
    __syncthreads();

    // out[i,g,o] = (sum_j p[j] * v2[j, g*64+o]) * isum + b_out
    const int o = tid & 63, ch = tid >> 6;
    const float* v2p = g_v2 + g * 64 + o;
    float a8[MI];
    #pragma unroll
    for (int ii = 0; ii < MI; ii++) a8[ii] = 0.f;
    for (int j = ch * 256; j < ch * 256 + 256; j++) {
        float v = v2p[(size_t)j * Dd];
        float4 pa = *(const float4*)&p_s[j][0];
        float4 pb = *(const float4*)&p_s[j][4];
        a8[0] += pa.x * v; a8[1] += pa.y * v;
        a8[2] += pa.z * v; a8[3] += pa.w * v;
        a8[4] += pb.x * v; a8[5] += pb.y * v;
        a8[6] += pb.z * v; a8[7] += pb.w * v;
    }
    #pragma unroll
    for (int ii = 0; ii < MI; ii++) oacc[ch][ii][o] = a8[ii];
    __syncthreads();

    for (int l = tid; l < MI * 64; l += 256) {
        int ii = l >> 6, oo = l & 63;
        float r = (oacc[0][ii][oo] + oacc[1][ii][oo] +
                   oacc[2][ii][oo] + oacc[3][ii][oo]) * isum[ii]
                  + bout[g * 64 + oo];
        out[(size_t)(i0 + ii) * Dd + g * 64 + oo] = r;
    }
}

// ---------------------------------------------------------------------------
extern "C" void kernel_launch(void* const* d_in, const int* in_sizes, int n_in,
                              void* d_out, int out_size) {
    const float* roi  = (const float*)d_in[0];
    const float* pe   = (const float*)d_in[1];
    const float* W1   = (const float*)d_in[2];
    const float* b1   = (const float*)d_in[3];
    const float* W2   = (const float*)d_in[4];
    const float* b2   = (const float*)d_in[5];
    const float* Wq   = (const float*)d_in[6];
    const float* bq   = (const float*)d_in[7];
    const float* Wk   = (const float*)d_in[8];
    const float* bk   = (const float*)d_in[9];
    const float* Wout = (const float*)d_in[10];
    const float* bout = (const float*)d_in[11];
    float* out = (float*)d_out;

    const int pe_smem = (4096 + 1024 + 64 + 16 + 128 * 65) * (int)sizeof(float);
    cudaFuncSetAttribute(k_pe, cudaFuncAttributeMaxDynamicSharedMemorySize, pe_smem);

    k_gemm3<<<dim3(16, 16, 3), 256>>>(roi, Wq, bq, Wk, bk, Wout);
    k_pe<<<(Nn * Nn) / 128, 128, pe_smem>>>(pe, W1, b1, W2, b2);
    k_attn<<<dim3(Nn / MI, Gg), 256>>>(bout, out);
}

// round 4
// speedup vs baseline: 1.8633x; 1.8633x over previous
#include <cuda_runtime.h>
#include <math.h>

#define Nn 1024
#define Dd 1024
#define Gg 16
#define MI 8

// Scratch (allocation-free rule: __device__ globals)
__device__ float g_q[Nn * Dd];                 // q[i, g*64+d]
__device__ float g_kT[Dd * Nn];                // kT[g*64+d, j]
__device__ float g_v2[Nn * Dd];                // v2[j, g*64+o]
__device__ float g_aff[(size_t)Nn * Gg * Nn];  // aff[i, g, j]

__device__ __forceinline__ unsigned f2tf(float x) {
    unsigned u; asm("cvt.rna.tf32.f32 %0, %1;" : "=r"(u) : "f"(x)); return u;
}
__device__ __forceinline__ void mma_tf32(float* c,
    unsigned a0, unsigned a1, unsigned a2, unsigned a3,
    unsigned b0, unsigned b1) {
    asm volatile(
        "mma.sync.aligned.m16n8k8.row.col.f32.tf32.tf32.f32 "
        "{%0,%1,%2,%3}, {%4,%5,%6,%7}, {%8,%9}, {%0,%1,%2,%3};\n"
        : "+f"(c[0]), "+f"(c[1]), "+f"(c[2]), "+f"(c[3])
        : "r"(a0), "r"(a1), "r"(a2), "r"(a3), "r"(b0), "r"(b1));
}

// ---------------------------------------------------------------------------
// K1: three 1024^3 GEMMs via 3xTF32 mma (z=0: Q, z=1: K^T, z=2: V2)
// Block tile 128x128, 8 warps (2x4), warp tile 64x32, K-stage 16, dbl-buffered.
// ---------------------------------------------------------------------------
#define K1_ASZ 2560   // 128*20 floats per A buffer
#define K1_BSZ 2112   // 16*132 floats per B buffer

__global__ void __launch_bounds__(256) k_gemm3(
    const float* __restrict__ roi,
    const float* __restrict__ Wq, const float* __restrict__ bq,
    const float* __restrict__ Wk, const float* __restrict__ bk,
    const float* __restrict__ Wout)
{
    extern __shared__ float sm1[];
    float* Ah = sm1;                    // 2 * 2560
    float* Al = Ah + 2 * K1_ASZ;        // 2 * 2560
    float* Bh = Al + 2 * K1_ASZ;        // 2 * 2112
    float* Bl = Bh + 2 * K1_BSZ;        // 2 * 2112

    const int z = blockIdx.z;
    const int rowBase = blockIdx.y * 128, colBase = blockIdx.x * 128;
    const int tid = threadIdx.x, lane = tid & 31, wid = tid >> 5;
    const int g = lane >> 2, tg = lane & 3;
    const int m_off = (wid >> 2) * 64, n_off = (wid & 3) * 32;
    const float* Bm = (z == 0) ? Wq : (z == 1) ? Wk : Wout;

    float acc[4][4][4] = {};

    const int ar = tid >> 2, ac4 = tid & 3;  // A LDG: rows ar, ar+64, float4 col ac4

    float4 aReg[2], bReg[2];

    // prefetch stage 0
    {
        const int k0 = 0;
        #pragma unroll
        for (int it = 0; it < 2; it++) {
            int r = ar + it * 64;
            aReg[it] = *(const float4*)&roi[(size_t)(rowBase + r) * 1024 + k0 + ac4 * 4];
        }
        #pragma unroll
        for (int it = 0; it < 2; it++) {
            int idx = tid + it * 256;
            int kr = idx >> 5, c4 = idx & 31;
            int col = colBase + c4 * 4;
            const float* src;
            if (z < 2) src = &Bm[(size_t)(k0 + kr) * 1024 + col];
            else { int gg = col >> 6, oo = col & 63; src = &Bm[((size_t)gg * 1024 + (k0 + kr)) * 64 + oo]; }
            bReg[it] = *(const float4*)src;
        }
        #pragma unroll
        for (int it = 0; it < 2; it++) {
            int r = ar + it * 64;
            float v[4] = {aReg[it].x, aReg[it].y, aReg[it].z, aReg[it].w};
            #pragma unroll
            for (int e = 0; e < 4; e++) {
                unsigned hi = f2tf(v[e]);
                float lo = v[e] - __uint_as_float(hi);
                Ah[r * 20 + ac4 * 4 + e] = __uint_as_float(hi);
                Al[r * 20 + ac4 * 4 + e] = __uint_as_float(f2tf(lo));
            }
        }
        #pragma unroll
        for (int it = 0; it < 2; it++) {
            int idx = tid + it * 256;
            int kr = idx >> 5, c4 = idx & 31;
            float v[4] = {bReg[it].x, bReg[it].y, bReg[it].z, bReg[it].w};
            #pragma unroll
            for (int e = 0; e < 4; e++) {
                unsigned hi = f2tf(v[e]);
                float lo = v[e] - __uint_as_float(hi);
                Bh[kr * 132 + c4 * 4 + e] = __uint_as_float(hi);
                Bl[kr * 132 + c4 * 4 + e] = __uint_as_float(f2tf(lo));
            }
        }
    }
    __syncthreads();

    for (int s = 0; s < 64; s++) {
        const int buf = s & 1;
        if (s < 63) {
            const int k0 = (s + 1) * 16;
            #pragma unroll
            for (int it = 0; it < 2; it++) {
                int r = ar + it * 64;
                aReg[it] = *(const float4*)&roi[(size_t)(rowBase + r) * 1024 + k0 + ac4 * 4];
            }
            #pragma unroll
            for (int it = 0; it < 2; it++) {
                int idx = tid + it * 256;
                int kr = idx >> 5, c4 = idx & 31;
                int col = colBase + c4 * 4;
                const float* src;
                if (z < 2) src = &Bm[(size_t)(k0 + kr) * 1024 + col];
                else { int gg = col >> 6, oo = col & 63; src = &Bm[((size_t)gg * 1024 + (k0 + kr)) * 64 + oo]; }
                bReg[it] = *(const float4*)src;
            }
        }

        // compute on buf
        const float* ah_b = Ah + buf * K1_ASZ;
        const float* al_b = Al + buf * K1_ASZ;
        const float* bh_b = Bh + buf * K1_BSZ;
        const float* bl_b = Bl + buf * K1_BSZ;
        #pragma unroll
        for (int kt = 0; kt < 2; kt++) {
            const int kb = kt * 8;
            unsigned ah[4][4], al[4][4];
            #pragma unroll
            for (int mt = 0; mt < 4; mt++) {
                const int rb = m_off + mt * 16;
                ah[mt][0] = __float_as_uint(ah_b[(rb + g) * 20 + kb + tg]);
                ah[mt][1] = __float_as_uint(ah_b[(rb + g + 8) * 20 + kb + tg]);
                ah[mt][2] = __float_as_uint(ah_b[(rb + g) * 20 + kb + tg + 4]);
                ah[mt][3] = __float_as_uint(ah_b[(rb + g + 8) * 20 + kb + tg + 4]);
                al[mt][0] = __float_as_uint(al_b[(rb + g) * 20 + kb + tg]);
                al[mt][1] = __float_as_uint(al_b[(rb + g + 8) * 20 + kb + tg]);
                al[mt][2] = __float_as_uint(al_b[(rb + g) * 20 + kb + tg + 4]);
                al[mt][3] = __float_as_uint(al_b[(rb + g + 8) * 20 + kb + tg + 4]);
            }
            #pragma unroll
            for (int nt = 0; nt < 4; nt++) {
                const int nb = n_off + nt * 8;
                unsigned bh0 = __float_as_uint(bh_b[(kb + tg) * 132 + nb + g]);
                unsigned bh1 = __float_as_uint(bh_b[(kb + tg + 4) * 132 + nb + g]);
                unsigned bl0 = __float_as_uint(bl_b[(kb + tg) * 132 + nb + g]);
                unsigned bl1 = __float_as_uint(bl_b[(kb + tg + 4) * 132 + nb + g]);
                #pragma unroll
                for (int mt = 0; mt < 4; mt++) {
                    mma_tf32(acc[mt][nt], ah[mt][0], ah[mt][1], ah[mt][2], ah[mt][3], bl0, bl1);
                    mma_tf32(acc[mt][nt], al[mt][0], al[mt][1], al[mt][2], al[mt][3], bh0, bh1);
                    mma_tf32(acc[mt][nt], ah[mt][0], ah[mt][1], ah[mt][2], ah[mt][3], bh0, bh1);
                }
            }
        }

        if (s < 63) {
            float* AhN = Ah + (buf ^ 1) * K1_ASZ;
            float* AlN = Al + (buf ^ 1) * K1_ASZ;
            float* BhN = Bh + (buf ^ 1) * K1_BSZ;
            float* BlN = Bl + (buf ^ 1) * K1_BSZ;
            #pragma unroll
            for (int it = 0; it < 2; it++) {
                int r = ar + it * 64;
                float v[4] = {aReg[it].x, aReg[it].y, aReg[it].z, aReg[it].w};
                #pragma unroll
                for (int e = 0; e < 4; e++) {
                    unsigned hi = f2tf(v[e]);
                    float lo = v[e] - __uint_as_float(hi);
                    AhN[r * 20 + ac4 * 4 + e] = __uint_as_float(hi);
                    AlN[r * 20 + ac4 * 4 + e] = __uint_as_float(f2tf(lo));
                }
            }
            #pragma unroll
            for (int it = 0; it < 2; it++) {
                int idx = tid + it * 256;
                int kr = idx >> 5, c4 = idx & 31;
                float v[4] = {bReg[it].x, bReg[it].y, bReg[it].z, bReg[it].w};
                #pragma unroll
                for (int e = 0; e < 4; e++) {
                    unsigned hi = f2tf(v[e]);
                    float lo = v[e] - __uint_as_float(hi);
                    BhN[kr * 132 + c4 * 4 + e] = __uint_as_float(hi);
                    BlN[kr * 132 + c4 * 4 + e] = __uint_as_float(f2tf(lo));
                }
            }
        }
        __syncthreads();
    }

    // epilogue
    #pragma unroll
    for (int mt = 0; mt < 4; mt++) {
        #pragma unroll
        for (int nt = 0; nt < 4; nt++) {
            #pragma unroll
            for (int e = 0; e < 4; e++) {
                int row = rowBase + m_off + mt * 16 + g + ((e >= 2) ? 8 : 0);
                int col = colBase + n_off + nt * 8 + 2 * tg + (e & 1);
                float v = acc[mt][nt][e];
                if (z == 0)      g_q[(size_t)row * 1024 + col] = v + bq[col];
                else if (z == 1) g_kT[(size_t)col * 1024 + row] = v + bk[col];
                else             g_v2[(size_t)row * 1024 + col] = v;
            }
        }
    }
}

// ---------------------------------------------------------------------------
// K2: PE MLP via tf32 mma. 256 rows/block, 8 warps x 32 rows.
// fc1 (64->64) mma, tanh, h restaged in smem (warp-local), fc2 (64->16) mma.
// ---------------------------------------------------------------------------
__global__ void __launch_bounds__(256) k_pe(
    const float* __restrict__ pe,
    const float* __restrict__ W1, const float* __restrict__ b1,
    const float* __restrict__ W2, const float* __restrict__ b2)
{
    extern __shared__ float sm2[];
    float* H   = sm2;            // 256*68 = 17408
    float* W1s = H + 17408;      // 64*72  = 4608
    float* W2s = W1s + 4608;     // 64*24  = 1536
    float* bb1 = W2s + 1536;     // 64
    float* bb2 = bb1 + 64;       // 16

    const int tid = threadIdx.x, lane = tid & 31, wid = tid >> 5;
    const int g = lane >> 2, tg = lane & 3;

    for (int l = tid; l < 4096; l += 256) {
        int k = l >> 6, n = l & 63;
        W1s[k * 72 + n] = __uint_as_float(f2tf(W1[l]));
    }
    for (int l = tid; l < 1024; l += 256) {
        int k = l >> 4, n = l & 15;
        W2s[k * 24 + n] = __uint_as_float(f2tf(W2[l]));
    }
    if (tid < 64) bb1[tid] = b1[tid];
    if (tid < 16) bb2[tid] = b2[tid];

    const size_t base = (size_t)blockIdx.x * 256 * 64;
    #pragma unroll
    for (int it = 0; it < 16; it++) {
        int idx = tid + it * 256;     // float4 index within 256x64 tile
        int r = idx >> 4, c4 = idx & 15;
        float4 v = *(const float4*)&pe[base + (size_t)idx * 4];
        float4 w;
        w.x = __uint_as_float(f2tf(v.x)); w.y = __uint_as_float(f2tf(v.y));
        w.z = __uint_as_float(f2tf(v.z)); w.w = __uint_as_float(f2tf(v.w));
        *(float4*)&H[r * 68 + c4 * 4] = w;
    }
    __syncthreads();

    const int rb0 = wid * 32;
    float acc[2][8][4] = {};
    #pragma unroll
    for (int kt = 0; kt < 8; kt++) {
        const int kb = kt * 8;
        unsigned a[2][4];
        #pragma unroll
        for (int mt = 0; mt < 2; mt++) {
            const int r = rb0 + mt * 16;
            a[mt][0] = __float_as_uint(H[(r + g) * 68 + kb + tg]);
            a[mt][1] = __float_as_uint(H[(r + g + 8) * 68 + kb + tg]);
            a[mt][2] = __float_as_uint(H[(r + g) * 68 + kb + tg + 4]);
            a[mt][3] = __float_as_uint(H[(r + g + 8) * 68 + kb + tg + 4]);
        }
        #pragma unroll
        for (int nt = 0; nt < 8; nt++) {
            unsigned b0 = __float_as_uint(W1s[(kb + tg) * 72 + nt * 8 + g]);
            unsigned b1r = __float_as_uint(W1s[(kb + tg + 4) * 72 + nt * 8 + g]);
            mma_tf32(acc[0][nt], a[0][0], a[0][1], a[0][2], a[0][3], b0, b1r);
            mma_tf32(acc[1][nt], a[1][0], a[1][1], a[1][2], a[1][3], b0, b1r);
        }
    }

    // bias + tanh, write h back into own rows of H (tf32-rounded)
    #pragma unroll
    for (int mt = 0; mt < 2; mt++) {
        const int r0 = rb0 + mt * 16 + g;
        #pragma unroll
        for (int nt = 0; nt < 8; nt++) {
            const int col = nt * 8 + 2 * tg;
            float h0 = tanhf(acc[mt][nt][0] + bb1[col]);
            float h1 = tanhf(acc[mt][nt][1] + bb1[col + 1]);
            float h2 = tanhf(acc[mt][nt][2] + bb1[col]);
            float h3 = tanhf(acc[mt][nt][3] + bb1[col + 1]);
            H[r0 * 68 + col]       = __uint_as_float(f2tf(h0));
            H[r0 * 68 + col + 1]   = __uint_as_float(f2tf(h1));
            H[(r0 + 8) * 68 + col]     = __uint_as_float(f2tf(h2));
            H[(r0 + 8) * 68 + col + 1] = __uint_as_float(f2tf(h3));
        }
    }
    __syncwarp();

    // fc2: h[32x64] @ W2[64x16]
    float acc2[2][2][4] = {};
    #pragma unroll
    for (int kt = 0; kt < 8; kt++) {
        const int kb = kt * 8;
        unsigned a[2][4];
        #pragma unroll
        for (int mt = 0; mt < 2; mt++) {
            const int r = rb0 + mt * 16;
            a[mt][0] = __float_as_uint(H[(r + g) * 68 + kb + tg]);
            a[mt][1] = __float_as_uint(H[(r + g + 8) * 68 + kb + tg]);
            a[mt][2] = __float_as_uint(H[(r + g) * 68 + kb + tg + 4]);
            a[mt][3] = __float_as_uint(H[(r + g + 8) * 68 + kb + tg + 4]);
        }
        #pragma unroll
        for (int nt = 0; nt < 2; nt++) {
            unsigned b0 = __float_as_uint(W2s[(kb + tg) * 24 + nt * 8 + g]);
            unsigned b1r = __float_as_uint(W2s[(kb + tg + 4) * 24 + nt * 8 + g]);
            mma_tf32(acc2[0][nt], a[0][0], a[0][1], a[0][2], a[0][3], b0, b1r);
            mma_tf32(acc2[1][nt], a[1][0], a[1][1], a[1][2], a[1][3], b0, b1r);
        }
    }

    const int growBase = blockIdx.x * 256;
    const int i = growBase >> 10;
    #pragma unroll
    for (int mt = 0; mt < 2; mt++) {
        #pragma unroll
        for (int nt = 0; nt < 2; nt++) {
            #pragma unroll
            for (int e = 0; e < 4; e++) {
                int grow = growBase + rb0 + mt * 16 + g + ((e >= 2) ? 8 : 0);
                int j = grow & 1023;
                int col = nt * 8 + 2 * tg + (e & 1);
                g_aff[((size_t)i * 16 + col) * 1024 + j] = acc2[mt][nt][e] + bb2[col];
            }
        }
    }
}

// ---------------------------------------------------------------------------
// K3: fused scores + softmax + P@V2 (unchanged from R2)
// ---------------------------------------------------------------------------
__global__ void __launch_bounds__(256) k_attn(
    const float* __restrict__ bout, float* __restrict__ out)
{
    const int g = blockIdx.y;
    const int i0 = blockIdx.x * MI;
    __shared__ float q_s[64][MI];
    __shared__ float p_s[1024][MI];
    __shared__ float red[MI][8];
    __shared__ float mval[MI], isum[MI];
    __shared__ float oacc[4][MI][64];
    const int tid = threadIdx.x;

    for (int l = tid; l < 64 * MI; l += 256) {
        int d = l >> 3, ii = l & 7;
        q_s[d][ii] = g_q[(size_t)(i0 + ii) * Dd + g * 64 + d];
    }
    __syncthreads();

    float s[MI][4];
    #pragma unroll
    for (int ii = 0; ii < MI; ii++)
        #pragma unroll
        for (int t = 0; t < 4; t++) s[ii][t] = 0.f;

    for (int d = 0; d < 64; d++) {
        const float* kr = g_kT + (size_t)(g * 64 + d) * Nn;
        float kv[4];
        #pragma unroll
        for (int t = 0; t < 4; t++) kv[t] = kr[tid + 256 * t];
        float4 qa = *(const float4*)&q_s[d][0];
        float4 qb = *(const float4*)&q_s[d][4];
        #pragma unroll
        for (int t = 0; t < 4; t++) {
            s[0][t] += qa.x * kv[t]; s[1][t] += qa.y * kv[t];
            s[2][t] += qa.z * kv[t]; s[3][t] += qa.w * kv[t];
            s[4][t] += qb.x * kv[t]; s[5][t] += qb.y * kv[t];
            s[6][t] += qb.z * kv[t]; s[7][t] += qb.w * kv[t];
        }
    }

    #pragma unroll
    for (int ii = 0; ii < MI; ii++) {
        const float* ar = g_aff + ((size_t)(i0 + ii) * 16 + g) * 1024;
        #pragma unroll
        for (int t = 0; t < 4; t++)
            s[ii][t] = ar[tid + 256 * t] * (s[ii][t] * 0.125f);
    }

    #pragma unroll
    for (int ii = 0; ii < MI; ii++) {
        float m = fmaxf(fmaxf(s[ii][0], s[ii][1]), fmaxf(s[ii][2], s[ii][3]));
        #pragma unroll
        for (int o = 16; o; o >>= 1) m = fmaxf(m, __shfl_xor_sync(0xffffffffu, m, o));
        if ((tid & 31) == 0) red[ii][tid >> 5] = m;
    }
    __syncthreads();
    if (tid < 64) {
        int ii = tid >> 3, w = tid & 7;
        float v = red[ii][w];
        #pragma unroll
        for (int o = 4; o; o >>= 1) v = fmaxf(v, __shfl_xor_sync(0xffffffffu, v, o));
        if (w == 0) mval[ii] = v;
    }
    __syncthreads();

    #pragma unroll
    for (int ii = 0; ii < MI; ii++) {
        float M = mval[ii];
        float su = 0.f;
        #pragma unroll
        for (int t = 0; t < 4; t++) {
            float ev = __expf(s[ii][t] - M);
            s[ii][t] = ev;
            su += ev;
        }
        #pragma unroll
        for (int o = 16; o; o >>= 1) su += __shfl_xor_sync(0xffffffffu, su, o);
        if ((tid & 31) == 0) red[ii][tid >> 5] = su;
    }
    __syncthreads();
    if (tid < 64) {
        int ii = tid >> 3, w = tid & 7;
        float v = red[ii][w];
        #pragma unroll
        for (int o = 4; o; o >>= 1) v += __shfl_xor_sync(0xffffffffu, v, o);
        if (w == 0) isum[ii] = 1.0f / v;
    }

    #pragma unroll
    for (int t = 0; t < 4; t++) {
        int j = tid + 256 * t;
        *(float4*)&p_s[j][0] = make_float4(s[0][t], s[1][t], s[2][t], s[3][t]);
        *(float4*)&p_s[j][4] = make_float4(s[4][t], s[5][t], s[6][t], s[7][t]);
    }
    __syncthreads();

    const int o = tid & 63, ch = tid >> 6;
    const float* v2p = g_v2 + g * 64 + o;
    float a8[MI];
    #pragma unroll
    for (int ii = 0; ii < MI; ii++) a8[ii] = 0.f;
    for (int j = ch * 256; j < ch * 256 + 256; j++) {
        float v = v2p[(size_t)j * Dd];
        float4 pa = *(const float4*)&p_s[j][0];
        float4 pb = *(const float4*)&p_s[j][4];
        a8[0] += pa.x * v; a8[1] += pa.y * v;
        a8[2] += pa.z * v; a8[3] += pa.w * v;
        a8[4] += pb.x * v; a8[5] += pb.y * v;
        a8[6] += pb.z * v; a8[7] += pb.w * v;
    }
    #pragma unroll
    for (int ii = 0; ii < MI; ii++) oacc[ch][ii][o] = a8[ii];
    __syncthreads();

    for (int l = tid; l < MI * 64; l += 256) {
        int ii = l >> 6, oo = l & 63;
        float r = (oacc[0][ii][oo] + oacc[1][ii][oo] +
                   oacc[2][ii][oo] + oacc[3][ii][oo]) * isum[ii]
                  + bout[g * 64 + oo];
        out[(size_t)(i0 + ii) * Dd + g * 64 + oo] = r;
    }
}

// ---------------------------------------------------------------------------
extern "C" void kernel_launch(void* const* d_in, const int* in_sizes, int n_in,
                              void* d_out, int out_size) {
    const float* roi  = (const float*)d_in[0];
    const float* pe   = (const float*)d_in[1];
    const float* W1   = (const float*)d_in[2];
    const float* b1   = (const float*)d_in[3];
    const float* W2   = (const float*)d_in[4];
    const float* b2   = (const float*)d_in[5];
    const float* Wq   = (const float*)d_in[6];
    const float* bq   = (const float*)d_in[7];
    const float* Wk   = (const float*)d_in[8];
    const float* bk   = (const float*)d_in[9];
    const float* Wout = (const float*)d_in[10];
    const float* bout = (const float*)d_in[11];
    float* out = (float*)d_out;

    const int g3_smem = (4 * K1_ASZ + 4 * K1_BSZ) * (int)sizeof(float);   // 74752
    const int pe_smem = (17408 + 4608 + 1536 + 64 + 16) * (int)sizeof(float);  // 94528
    cudaFuncSetAttribute(k_gemm3, cudaFuncAttributeMaxDynamicSharedMemorySize, g3_smem);
    cudaFuncSetAttribute(k_pe, cudaFuncAttributeMaxDynamicSharedMemorySize, pe_smem);

    k_gemm3<<<dim3(8, 8, 3), 256, g3_smem>>>(roi, Wq, bq, Wk, bk, Wout);
    k_pe<<<(Nn * Nn) / 256, 256, pe_smem>>>(pe, W1, b1, W2, b2);
    k_attn<<<dim3(Nn / MI, Gg), 256>>>(bout, out);
}